// round 7
// baseline (speedup 1.0000x reference)
#include <cuda_runtime.h>
#include <cuda_bf16.h>
#include <cstdint>
#include <math.h>

// Problem constants
#define BATCH   2
#define SEQ     2048
#define HID     1024
#define NHEADS  16
#define HD      64
#define QKV_N   3072
#define MROWS   4096
#define KS8     3072          // stacked int8 K = 3*1024 bytes

#define QSCALE  0.18033688f   // 0.125 * log2(e)

// ---------------- scratch (device globals; no allocations allowed) ----------
__device__ int8_t g_x8[(size_t)MROWS * KS8];                  // [a0|a1|a0] per row
__device__ float  g_sa[MROWS];
__device__ int8_t g_wq8[(size_t)QKV_N * KS8];                 // [b0|b0|b1] per out-col
__device__ int8_t g_wo8[(size_t)HID * KS8];
__device__ float  g_sbq[QKV_N];
__device__ float  g_sbo[HID];
__device__ int    g_wqmax[QKV_N];
__device__ int    g_womax[HID];
__device__ float  g_attn[(size_t)MROWS * HID];                // attention out fp32
// Head-major bf16 hi/lo Q/K/V: [b*16+h][s][64]
#define HM_ELEMS ((size_t)BATCH * NHEADS * SEQ * HD)
__device__ __nv_bfloat16 g_qh[HM_ELEMS], g_ql[HM_ELEMS];
__device__ __nv_bfloat16 g_kh[HM_ELEMS], g_kl[HM_ELEMS];
__device__ __nv_bfloat16 g_vh[HM_ELEMS], g_vl[HM_ELEMS];

// ---------------- PTX helpers (base ISA only) ----------------
__device__ __forceinline__ uint32_t smem_u32(const void* p) {
    uint32_t a;
    asm("{ .reg .u64 t; cvta.to.shared.u64 t, %1; cvt.u32.u64 %0, t; }" : "=r"(a) : "l"(p));
    return a;
}

__device__ __forceinline__ void cp_async16(uint32_t s, const void* g) {
    asm volatile("cp.async.cg.shared.global [%0], [%1], 16;" :: "r"(s), "l"(g) : "memory");
}
#define CP_COMMIT() asm volatile("cp.async.commit_group;" ::: "memory")
#define CP_WAIT1()  asm volatile("cp.async.wait_group 1;"  ::: "memory")

#define LDSM_X4(R0, R1, R2, R3, ADDR)                                          \
    asm volatile("ldmatrix.sync.aligned.m8n8.x4.shared.b16 {%0,%1,%2,%3}, [%4];" \
                 : "=r"(R0), "=r"(R1), "=r"(R2), "=r"(R3) : "r"(ADDR))

#define LDSM_X4T(R0, R1, R2, R3, ADDR)                                         \
    asm volatile("ldmatrix.sync.aligned.m8n8.x4.trans.shared.b16 {%0,%1,%2,%3}, [%4];" \
                 : "=r"(R0), "=r"(R1), "=r"(R2), "=r"(R3) : "r"(ADDR))

#define MMA16816(D, A, B0, B1)                                                 \
    asm volatile("mma.sync.aligned.m16n8k16.row.col.f32.bf16.bf16.f32 "        \
                 "{%0,%1,%2,%3},{%4,%5,%6,%7},{%8,%9},{%0,%1,%2,%3};"          \
                 : "+f"((D)[0]), "+f"((D)[1]), "+f"((D)[2]), "+f"((D)[3])      \
                 : "r"((A)[0]), "r"((A)[1]), "r"((A)[2]), "r"((A)[3]),         \
                   "r"(B0), "r"(B1))

#define IMMA16832(D, A, B0, B1)                                                \
    asm volatile("mma.sync.aligned.m16n8k32.row.col.s32.s8.s8.s32 "            \
                 "{%0,%1,%2,%3},{%4,%5,%6,%7},{%8,%9},{%0,%1,%2,%3};"          \
                 : "+r"((D)[0]), "+r"((D)[1]), "+r"((D)[2]), "+r"((D)[3])      \
                 : "r"((A)[0]), "r"((A)[1]), "r"((A)[2]), "r"((A)[3]),         \
                   "r"(B0), "r"(B1))

// Fast exp2 on FMA/ALU pipes (no MUFU). rel err ~1e-7.
__device__ __forceinline__ float fexp2(float x) {
    x = fmaxf(x, -125.0f);
    int   n  = __float2int_rn(x);
    float f  = x - (float)n;
    float p  = 1.535336188319500e-4f;
    p = fmaf(p, f, 1.339887440266574e-3f);
    p = fmaf(p, f, 9.618437357674640e-3f);
    p = fmaf(p, f, 5.550332471162809e-2f);
    p = fmaf(p, f, 2.402264791363012e-1f);
    p = fmaf(p, f, 6.931472028550421e-1f);
    p = fmaf(p, f, 1.0f);
    return __int_as_float(__float_as_int(p) + (n << 23));
}

__device__ __forceinline__ uint32_t packbf2(__nv_bfloat16 a, __nv_bfloat16 b) {
    __nv_bfloat162 t;
    t.x = a; t.y = b;
    return *reinterpret_cast<uint32_t*>(&t);
}

__device__ __forceinline__ int clamp127(int v) {
    return max(-127, min(127, v));
}

// ---------------------------------------------------------------------------
// Per-output-column |max| of W [1024, N] via atomicMax on float bits.
// grid (N/256, 16); each thread covers 64 k's of one column.
// ---------------------------------------------------------------------------
__global__ __launch_bounds__(256) void wmax_kernel(
    const float* __restrict__ w, int* __restrict__ bits, int N)
{
    const int n  = blockIdx.x * 256 + threadIdx.x;
    const int k0 = blockIdx.y * 64;
    float m = 0.0f;
#pragma unroll 8
    for (int i = 0; i < 64; i++)
        m = fmaxf(m, fabsf(w[(size_t)(k0 + i) * N + n]));
    atomicMax(bits + n, __float_as_int(m));
}

// ---------------------------------------------------------------------------
// Quantize + transpose W [1024, N] -> int8 stacked [N][3072] = [b0|b0|b1].
// ---------------------------------------------------------------------------
__global__ __launch_bounds__(1024) void wquant_kernel(
    const float* __restrict__ w, const int* __restrict__ bits,
    int8_t* __restrict__ out, float* __restrict__ sbf, int N)
{
    __shared__ float tile[32][33];
    const int tx = threadIdx.x & 31;
    const int ty = threadIdx.x >> 5;
    const int gn = blockIdx.x * 32;
    const int gk = blockIdx.y * 32;
    tile[ty][tx] = w[(size_t)(gk + ty) * N + gn + tx];
    __syncthreads();
    const float v  = tile[tx][ty];                   // (k = gk+tx, n = gn+ty)
    const float mx = fmaxf(__int_as_float(bits[gn + ty]), 1e-20f);
    const float inv = 127.0f / mx;
    const float f   = v * inv;
    const float a0f = rintf(f);
    const int   a0  = (int)a0f;
    const int   a1  = clamp127((int)rintf((f - a0f) * 256.0f));
    const size_t o = (size_t)(gn + ty) * KS8 + gk + tx;
    out[o]        = (int8_t)a0;
    out[o + 1024] = (int8_t)a0;
    out[o + 2048] = (int8_t)a1;
    if (blockIdx.y == 0 && tx == 0)
        sbf[gn + ty] = mx * (1.0f / 127.0f);
}

// ---------------------------------------------------------------------------
// Quantize activations fp32 [R][1024] -> int8 stacked [R][3072] = [a0|a1|a0],
// per-row scale. One block per row.
// ---------------------------------------------------------------------------
__global__ __launch_bounds__(256) void quant_act_kernel(
    const float* __restrict__ in, int8_t* __restrict__ out, float* __restrict__ sa)
{
    __shared__ float red[8];
    const int row = blockIdx.x;
    const int t   = threadIdx.x;
    const float4 x = ((const float4*)(in + (size_t)row * 1024))[t];
    float m = fmaxf(fmaxf(fabsf(x.x), fabsf(x.y)), fmaxf(fabsf(x.z), fabsf(x.w)));
#pragma unroll
    for (int o = 16; o > 0; o >>= 1)
        m = fmaxf(m, __shfl_xor_sync(0xffffffffu, m, o));
    if ((t & 31) == 0) red[t >> 5] = m;
    __syncthreads();
    m = red[0];
#pragma unroll
    for (int i = 1; i < 8; i++) m = fmaxf(m, red[i]);
    m = fmaxf(m, 1e-20f);
    const float inv = 127.0f / m;

    float f[4] = { x.x * inv, x.y * inv, x.z * inv, x.w * inv };
    signed char c0[4], c1[4];
#pragma unroll
    for (int i = 0; i < 4; i++) {
        const float a0f = rintf(f[i]);
        c0[i] = (signed char)(int)a0f;
        c1[i] = (signed char)clamp127((int)rintf((f[i] - a0f) * 256.0f));
    }
    char4 v0 = { c0[0], c0[1], c0[2], c0[3] };
    char4 v1 = { c1[0], c1[1], c1[2], c1[3] };
    ((char4*)(out + (size_t)row * KS8))[t]        = v0;
    ((char4*)(out + (size_t)row * KS8 + 1024))[t] = v1;
    ((char4*)(out + (size_t)row * KS8 + 2048))[t] = v0;
    if (t == 0) sa[row] = m * (1.0f / 127.0f);
}

// ---------------------------------------------------------------------------
// IMMA GEMM: C[4096,N] = dequant( As8[4096,3072] @ Bs8[N,3072]^T ) + bias.
// CTA tile 128x64xBK128 (bytes), 256 threads (8 warps, 4x2), warp tile 32x32.
// Phase split: iters 0-7 -> a0b0 (unit); iters 8-23 -> cross terms (1/256).
// mode 0: fp32 C out.  mode 1: QKV epilogue -> bf16 hi/lo head-major Q/K/V.
// ---------------------------------------------------------------------------
#define BM8 128
#define BN8 64
#define BK8 128
#define NKIT8 (KS8 / BK8)                  // 24
#define A8_BYTES (BM8 * 128)               // 16 KB
#define B8_BYTES (BN8 * 128)               // 8 KB
#define STAGE8   (A8_BYTES + B8_BYTES)     // 24 KB
#define GEMM8_SMEM (3 * STAGE8 + 128)

__global__ __launch_bounds__(256, 2) void imma_gemm_kernel(
    const int8_t* __restrict__ As, const int8_t* __restrict__ Bs,
    const float* __restrict__ sa, const float* __restrict__ sb,
    const float* __restrict__ bias, float* __restrict__ C, int N, int mode,
    __nv_bfloat16* __restrict__ qh, __nv_bfloat16* __restrict__ ql,
    __nv_bfloat16* __restrict__ kh, __nv_bfloat16* __restrict__ kl,
    __nv_bfloat16* __restrict__ vh, __nv_bfloat16* __restrict__ vl)
{
    extern __shared__ char dsmem[];
    const uint32_t smem_base = (smem_u32(dsmem) + 127u) & ~127u;

    const int tid  = threadIdx.x;
    const int wid  = tid >> 5;
    const int lane = tid & 31;
    const int wm   = wid >> 1;     // 0..3 (32-row slab)
    const int wn   = wid & 1;      // 0..1 (32-col slab)

    const int block_row = blockIdx.y * BM8;
    const int block_col = blockIdx.x * BN8;

    const int8_t* Abase = As + (size_t)block_row * KS8;
    const int8_t* Bbase = Bs + (size_t)block_col * KS8;

    auto load_stage = [&](int stage, int kc) {
        const uint32_t sA = smem_base + stage * STAGE8;
        const uint32_t sB = sA + A8_BYTES;
#pragma unroll
        for (int i = 0; i < 4; i++) {       // A: 1024 segs
            const int s   = i * 256 + tid;
            const int row = s >> 3;
            const int ch  = s & 7;
            const uint32_t sw = (uint32_t)(ch * 16) ^ (uint32_t)((row & 7) << 4);
            cp_async16(sA + row * 128 + sw, Abase + (size_t)row * KS8 + kc + ch * 16);
        }
#pragma unroll
        for (int i = 0; i < 2; i++) {       // B: 512 segs
            const int s   = i * 256 + tid;
            const int row = s >> 3;
            const int ch  = s & 7;
            const uint32_t sw = (uint32_t)(ch * 16) ^ (uint32_t)((row & 7) << 4);
            cp_async16(sB + row * 128 + sw, Bbase + (size_t)row * KS8 + kc + ch * 16);
        }
        CP_COMMIT();
    };

    int   iacc[2][4][4];
    float facc[2][4][4];
#pragma unroll
    for (int mt = 0; mt < 2; mt++)
#pragma unroll
        for (int nt = 0; nt < 4; nt++)
#pragma unroll
            for (int r = 0; r < 4; r++) { iacc[mt][nt][r] = 0; facc[mt][nt][r] = 0.0f; }

    load_stage(0, 0);
    load_stage(1, BK8);

    const int lrow  = lane & 15;
    const int kseg  = (lane >> 4) * 16;
    const uint32_t arow_off = (uint32_t)(wm * 32 + lrow) * 128;
    const uint32_t brow_off = (uint32_t)(wn * 32 + lrow) * 128;
    const uint32_t aswz = (uint32_t)((lrow & 7) << 4);

    auto do_iter = [&](int it) {
        CP_WAIT1();
        __syncthreads();
        if (it + 2 < NKIT8) load_stage((it + 2) % 3, (it + 2) * BK8);
        else                CP_COMMIT();

        const uint32_t sA = smem_base + (it % 3) * STAGE8;
        const uint32_t sB = sA + A8_BYTES;

#pragma unroll
        for (int kt = 0; kt < 4; kt++) {
            const uint32_t koff = ((uint32_t)(kt * 32 + kseg)) ^ aswz;
            uint32_t a[2][4], bb[2][4];
#pragma unroll
            for (int mt = 0; mt < 2; mt++)
                LDSM_X4(a[mt][0], a[mt][1], a[mt][2], a[mt][3],
                        sA + arow_off + (uint32_t)(mt * 16 * 128) + koff);
#pragma unroll
            for (int pr = 0; pr < 2; pr++)
                LDSM_X4(bb[pr][0], bb[pr][1], bb[pr][2], bb[pr][3],
                        sB + brow_off + (uint32_t)(pr * 16 * 128) + koff);
#pragma unroll
            for (int mt = 0; mt < 2; mt++)
#pragma unroll
                for (int nt = 0; nt < 4; nt++) {
                    const int pr = nt >> 1, sub = nt & 1;
                    IMMA16832(iacc[mt][nt], a[mt], bb[pr][sub], bb[pr][sub + 2]);
                }
        }
    };

    for (int it = 0; it < 8; it++) do_iter(it);         // a0*b0
    // fold unit-scale phase into float, reset int accumulators
#pragma unroll
    for (int mt = 0; mt < 2; mt++)
#pragma unroll
        for (int nt = 0; nt < 4; nt++)
#pragma unroll
            for (int r = 0; r < 4; r++) {
                facc[mt][nt][r] = (float)iacc[mt][nt][r];
                iacc[mt][nt][r] = 0;
            }
    for (int it = 8; it < NKIT8; it++) do_iter(it);     // a1*b0 + a0*b1

    const int rbase = block_row + wm * 32 + (lane >> 2);
    const int cbase = block_col + wn * 32 + (lane & 3) * 2;

#pragma unroll
    for (int mt = 0; mt < 2; mt++) {
#pragma unroll
        for (int nt = 0; nt < 4; nt++) {
            const int col = cbase + nt * 8;
            const float sb0 = sb[col];
            const float sb1 = sb[col + 1];
            const float bx  = bias[col];
            const float by  = bias[col + 1];
            if (mode == 0) {
#pragma unroll
                for (int rr = 0; rr < 2; rr++) {
                    const int r = rbase + mt * 16 + rr * 8;
                    const float saf = sa[r];
                    const float v0 = saf * sb0 *
                        (facc[mt][nt][rr * 2] + (float)iacc[mt][nt][rr * 2] * 0.00390625f) + bx;
                    const float v1 = saf * sb1 *
                        (facc[mt][nt][rr * 2 + 1] + (float)iacc[mt][nt][rr * 2 + 1] * 0.00390625f) + by;
                    float2 o = { v0, v1 };
                    *(float2*)(C + (size_t)r * N + col) = o;
                }
            } else {
                const int part = col >> 10;           // CTA-uniform (BN=64 within a head)
                const int hh   = (col >> 6) & 15;
                const int dd   = col & 63;
                __nv_bfloat16* dh = part == 0 ? qh : (part == 1 ? kh : vh);
                __nv_bfloat16* dl = part == 0 ? ql : (part == 1 ? kl : vl);
                const float sc = part == 0 ? QSCALE : 1.0f;
#pragma unroll
                for (int rr = 0; rr < 2; rr++) {
                    const int r = rbase + mt * 16 + rr * 8;
                    const float saf = sa[r];
                    const float v0 = (saf * sb0 *
                        (facc[mt][nt][rr * 2] + (float)iacc[mt][nt][rr * 2] * 0.00390625f) + bx) * sc;
                    const float v1 = (saf * sb1 *
                        (facc[mt][nt][rr * 2 + 1] + (float)iacc[mt][nt][rr * 2 + 1] * 0.00390625f) + by) * sc;
                    const __nv_bfloat16 h0 = __float2bfloat16(v0);
                    const __nv_bfloat16 h1 = __float2bfloat16(v1);
                    const size_t off =
                        (((size_t)((r >> 11) * 16 + hh)) * SEQ + (r & 2047)) * 64 + dd;
                    *(uint32_t*)(dh + off) = packbf2(h0, h1);
                    *(uint32_t*)(dl + off) =
                        packbf2(__float2bfloat16(v0 - __bfloat162float(h0)),
                                __float2bfloat16(v1 - __bfloat162float(h1)));
                }
            }
        }
    }
}

// ---------------------------------------------------------------------------
// HMMA causal flash attention, bf16-fed, 3-stage cp.async pipeline.
// One CTA = 128 queries of one (b,h); 8 warps x 16 rows; 64-key tiles.
// Output: fp32 g_attn [4096][1024].
// smem: QH 16K | QL 16K | 3 stages x {KH,KL,VH,VL 8K each} = 128KB
// ---------------------------------------------------------------------------
#define KV_STAGE_BYTES 32768
#define ATTN_SMEM (32768 + 3 * KV_STAGE_BYTES + 128)

__global__ __launch_bounds__(256) void attn_mma_kernel(
    const __nv_bfloat16* __restrict__ qh_g, const __nv_bfloat16* __restrict__ ql_g,
    const __nv_bfloat16* __restrict__ kh_g, const __nv_bfloat16* __restrict__ kl_g,
    const __nv_bfloat16* __restrict__ vh_g, const __nv_bfloat16* __restrict__ vl_g,
    float* __restrict__ outf)
{
    extern __shared__ char sm[];
    const uint32_t base = (smem_u32(sm) + 127u) & ~127u;
    const uint32_t sQH = base;
    const uint32_t sQL = base + 16384;
    const uint32_t kvbase = base + 32768;

    const int tid  = threadIdx.x;
    const int lane = tid & 31;
    const int wid  = tid >> 5;
    const int qb   = 15 - (int)blockIdx.x;     // heavy blocks first
    const int bh   = blockIdx.y;
    const int b    = bh >> 4;
    const int h    = bh & 15;
    const size_t hrow = (size_t)bh * SEQ;

    // ---- Q tile cp.async (part of group 0) ----
#pragma unroll
    for (int i = 0; i < 4; i++) {
        const int s   = i * 256 + tid;
        const int row = s >> 3;
        const int ch  = s & 7;
        const uint32_t sw = (uint32_t)(ch * 16) ^ (uint32_t)((row & 7) << 4);
        const size_t gofs = (hrow + qb * 128 + row) * 64 + ch * 8;
        cp_async16(sQH + row * 128 + sw, qh_g + gofs);
        cp_async16(sQL + row * 128 + sw, ql_g + gofs);
    }

    auto load_kv = [&](int stage, int k0) {
        const uint32_t sb = kvbase + stage * KV_STAGE_BYTES;
#pragma unroll
        for (int i = 0; i < 2; i++) {
            const int s   = i * 256 + tid;
            const int row = s >> 3;
            const int ch  = s & 7;
            const uint32_t sw = (uint32_t)(ch * 16) ^ (uint32_t)((row & 7) << 4);
            const uint32_t so = row * 128 + sw;
            const size_t gofs = (hrow + k0 + row) * 64 + ch * 8;
            cp_async16(sb + so,         kh_g + gofs);
            cp_async16(sb + 8192 + so,  kl_g + gofs);
            cp_async16(sb + 16384 + so, vh_g + gofs);
            cp_async16(sb + 24576 + so, vl_g + gofs);
        }
        CP_COMMIT();
    };

    const int nk = (qb + 1) * 2;
    load_kv(0, 0);
    load_kv(1, 64);

    float acc_o[8][4];
#pragma unroll
    for (int nt = 0; nt < 8; nt++)
#pragma unroll
        for (int r = 0; r < 4; r++) acc_o[nt][r] = 0.0f;
    float m0 = -1e30f, m1 = -1e30f, l0 = 0.0f, l1 = 0.0f;

    const int r0      = lane >> 2;
    const int qrow_w  = qb * 128 + wid * 16;
    const int qg0     = qrow_w + r0;

    const int a_r = wid * 16 + (lane & 15);
    const int a_c = (lane >> 4) * 16;
    const uint32_t a_row_off = (uint32_t)(a_r * 128);
    const uint32_t a_sw = (uint32_t)((a_r & 7) << 4);
    const int g      = lane >> 3;
    const int br_off = lane & 7;

    for (int t = 0; t < nk; t++) {
        const int k0 = t * 64;
        CP_WAIT1();
        __syncthreads();
        if (t + 2 < nk) load_kv((t + 2) % 3, (t + 2) * 64);
        else            CP_COMMIT();

        const uint32_t st  = kvbase + (t % 3) * KV_STAGE_BYTES;
        const uint32_t sKH = st;
        const uint32_t sKL = st + 8192;
        const uint32_t sVH = st + 16384;
        const uint32_t sVL = st + 24576;

        // ---- S = Q K^T (3-pass hi/lo) ----
        float s[8][4];
#pragma unroll
        for (int nt = 0; nt < 8; nt++)
#pragma unroll
            for (int r = 0; r < 4; r++) s[nt][r] = 0.0f;

#pragma unroll
        for (int kc = 0; kc < 4; kc++) {
            uint32_t qhf[4], qlf[4];
            const uint32_t qoff = ((uint32_t)(kc * 32 + a_c)) ^ a_sw;
            LDSM_X4(qhf[0], qhf[1], qhf[2], qhf[3], sQH + a_row_off + qoff);
            LDSM_X4(qlf[0], qlf[1], qlf[2], qlf[3], sQL + a_row_off + qoff);
#pragma unroll
            for (int np = 0; np < 4; np++) {
                const int brow = np * 16 + ((g & 2) << 2) + br_off;
                const uint32_t boff = ((uint32_t)(kc * 32 + ((g & 1) << 4)))
                                    ^ (uint32_t)((brow & 7) << 4);
                const uint32_t rb = (uint32_t)(brow * 128) + boff;
                uint32_t b0, b1, b2, b3;
                LDSM_X4(b0, b1, b2, b3, sKH + rb);
                MMA16816(s[2 * np],     qhf, b0, b1);
                MMA16816(s[2 * np + 1], qhf, b2, b3);
                MMA16816(s[2 * np],     qlf, b0, b1);
                MMA16816(s[2 * np + 1], qlf, b2, b3);
                LDSM_X4(b0, b1, b2, b3, sKL + rb);
                MMA16816(s[2 * np],     qhf, b0, b1);
                MMA16816(s[2 * np + 1], qhf, b2, b3);
            }
        }

        // ---- causal mask ----
        if (k0 + 63 > qrow_w) {
#pragma unroll
            for (int nt = 0; nt < 8; nt++) {
                const int kg0 = k0 + nt * 8 + 2 * (lane & 3);
                if (kg0     > qg0)     s[nt][0] = -1e30f;
                if (kg0 + 1 > qg0)     s[nt][1] = -1e30f;
                if (kg0     > qg0 + 8) s[nt][2] = -1e30f;
                if (kg0 + 1 > qg0 + 8) s[nt][3] = -1e30f;
            }
        }

        // ---- online softmax (base-2) ----
        float rx0 = -1e30f, rx1 = -1e30f;
#pragma unroll
        for (int nt = 0; nt < 8; nt++) {
            rx0 = fmaxf(rx0, fmaxf(s[nt][0], s[nt][1]));
            rx1 = fmaxf(rx1, fmaxf(s[nt][2], s[nt][3]));
        }
        rx0 = fmaxf(rx0, __shfl_xor_sync(0xffffffffu, rx0, 1));
        rx0 = fmaxf(rx0, __shfl_xor_sync(0xffffffffu, rx0, 2));
        rx1 = fmaxf(rx1, __shfl_xor_sync(0xffffffffu, rx1, 1));
        rx1 = fmaxf(rx1, __shfl_xor_sync(0xffffffffu, rx1, 2));
        const float mn0 = fmaxf(m0, rx0);
        const float mn1 = fmaxf(m1, rx1);
        const float sc0 = fexp2(m0 - mn0);
        const float sc1 = fexp2(m1 - mn1);
        m0 = mn0; m1 = mn1;
        l0 *= sc0; l1 *= sc1;
#pragma unroll
        for (int nt = 0; nt < 8; nt++) {
            acc_o[nt][0] *= sc0; acc_o[nt][1] *= sc0;
            acc_o[nt][2] *= sc1; acc_o[nt][3] *= sc1;
        }

        uint32_t ph[4][4], pl[4][4];
#pragma unroll
        for (int nt = 0; nt < 8; nt++) {
            const float p0 = fexp2(s[nt][0] - m0);
            const float p1 = fexp2(s[nt][1] - m0);
            const float p2 = fexp2(s[nt][2] - m1);
            const float p3 = fexp2(s[nt][3] - m1);
            l0 += p0 + p1;
            l1 += p2 + p3;
            const __nv_bfloat16 h0 = __float2bfloat16(p0);
            const __nv_bfloat16 h1 = __float2bfloat16(p1);
            const __nv_bfloat16 h2 = __float2bfloat16(p2);
            const __nv_bfloat16 h3 = __float2bfloat16(p3);
            const int kc = nt >> 1;
            const int rr = (nt & 1) * 2;
            ph[kc][rr]     = packbf2(h0, h1);
            ph[kc][rr + 1] = packbf2(h2, h3);
            pl[kc][rr]     = packbf2(__float2bfloat16(p0 - __bfloat162float(h0)),
                                     __float2bfloat16(p1 - __bfloat162float(h1)));
            pl[kc][rr + 1] = packbf2(__float2bfloat16(p2 - __bfloat162float(h2)),
                                     __float2bfloat16(p3 - __bfloat162float(h3)));
        }

        // ---- O += P V (3-pass hi/lo, ldmatrix.trans for V) ----
#pragma unroll
        for (int kc = 0; kc < 4; kc++) {
#pragma unroll
            for (int np = 0; np < 4; np++) {
                const int vrow = kc * 16 + ((g & 1) << 3) + br_off;
                const uint32_t voff = ((uint32_t)(np * 32 + ((g & 2) << 3)))
                                    ^ (uint32_t)((vrow & 7) << 4);
                const uint32_t rv = (uint32_t)(vrow * 128) + voff;
                uint32_t b0, b1, b2, b3;
                LDSM_X4T(b0, b1, b2, b3, sVH + rv);
                MMA16816(acc_o[2 * np],     ph[kc], b0, b1);
                MMA16816(acc_o[2 * np + 1], ph[kc], b2, b3);
                MMA16816(acc_o[2 * np],     pl[kc], b0, b1);
                MMA16816(acc_o[2 * np + 1], pl[kc], b2, b3);
                LDSM_X4T(b0, b1, b2, b3, sVL + rv);
                MMA16816(acc_o[2 * np],     ph[kc], b0, b1);
                MMA16816(acc_o[2 * np + 1], ph[kc], b2, b3);
            }
        }
        // NOTE: trailing __syncthreads removed — the top-of-loop barrier
        // already orders stage reuse (write target (t+2)%3 never collides
        // with a stage still being read).
    }

    // ---- epilogue: normalize, write fp32 rows of g_attn ----
    l0 += __shfl_xor_sync(0xffffffffu, l0, 1);
    l0 += __shfl_xor_sync(0xffffffffu, l0, 2);
    l1 += __shfl_xor_sync(0xffffffffu, l1, 1);
    l1 += __shfl_xor_sync(0xffffffffu, l1, 2);
    const float inv0 = 1.0f / l0;
    const float inv1 = 1.0f / l1;

    float* op = outf + ((size_t)(b * SEQ + qg0)) * HID + h * HD + 2 * (lane & 3);
#pragma unroll
    for (int nt = 0; nt < 8; nt++) {
        float2 o0 = { acc_o[nt][0] * inv0, acc_o[nt][1] * inv0 };
        float2 o1 = { acc_o[nt][2] * inv1, acc_o[nt][3] * inv1 };
        *(float2*)(op + nt * 8)            = o0;
        *(float2*)(op + 8 * HID + nt * 8)  = o1;
    }
}

// ---------------------------------------------------------------------------
extern "C" void kernel_launch(void* const* d_in, const int* in_sizes, int n_in,
                              void* d_out, int out_size)
{
    const float* x     = (const float*)d_in[0];
    const float* w_qkv = (const float*)d_in[1];
    const float* b_qkv = (const float*)d_in[2];
    const float* w_out = (const float*)d_in[3];
    const float* b_out = (const float*)d_in[4];
    float* out = (float*)d_out;

    int8_t *x8, *wq8, *wo8;
    float *sa, *sbq, *sbo, *attn;
    int *wqmax, *womax;
    __nv_bfloat16 *qh, *ql, *kh, *kl, *vh, *vl;
    cudaGetSymbolAddress((void**)&x8,    g_x8);
    cudaGetSymbolAddress((void**)&sa,    g_sa);
    cudaGetSymbolAddress((void**)&wq8,   g_wq8);
    cudaGetSymbolAddress((void**)&wo8,   g_wo8);
    cudaGetSymbolAddress((void**)&sbq,   g_sbq);
    cudaGetSymbolAddress((void**)&sbo,   g_sbo);
    cudaGetSymbolAddress((void**)&wqmax, g_wqmax);
    cudaGetSymbolAddress((void**)&womax, g_womax);
    cudaGetSymbolAddress((void**)&attn,  g_attn);
    cudaGetSymbolAddress((void**)&qh, g_qh);
    cudaGetSymbolAddress((void**)&ql, g_ql);
    cudaGetSymbolAddress((void**)&kh, g_kh);
    cudaGetSymbolAddress((void**)&kl, g_kl);
    cudaGetSymbolAddress((void**)&vh, g_vh);
    cudaGetSymbolAddress((void**)&vl, g_vl);

    cudaFuncSetAttribute(imma_gemm_kernel,
                         cudaFuncAttributeMaxDynamicSharedMemorySize, GEMM8_SMEM);
    cudaFuncSetAttribute(attn_mma_kernel,
                         cudaFuncAttributeMaxDynamicSharedMemorySize, ATTN_SMEM);

    // 0) zero col-max accumulators
    cudaMemsetAsync(wqmax, 0, QKV_N * sizeof(int));
    cudaMemsetAsync(womax, 0, HID * sizeof(int));

    // 1) weight col maxes
    {
        dim3 grid(QKV_N / 256, 16);
        wmax_kernel<<<grid, 256>>>(w_qkv, wqmax, QKV_N);
    }
    {
        dim3 grid(HID / 256, 16);
        wmax_kernel<<<grid, 256>>>(w_out, womax, HID);
    }
    // 2) weight quantize + transpose (stacked [b0|b0|b1])
    {
        dim3 grid(QKV_N / 32, HID / 32);
        wquant_kernel<<<grid, 1024>>>(w_qkv, wqmax, wq8, sbq, QKV_N);
    }
    {
        dim3 grid(HID / 32, HID / 32);
        wquant_kernel<<<grid, 1024>>>(w_out, womax, wo8, sbo, HID);
    }
    // 3) quantize x (stacked [a0|a1|a0])
    quant_act_kernel<<<MROWS, 256>>>(x, x8, sa);
    // 4) int8 QKV projection -> head-major bf16 hi/lo Q/K/V (mode 1)
    {
        dim3 grid(QKV_N / BN8, MROWS / BM8);
        imma_gemm_kernel<<<grid, 256, GEMM8_SMEM>>>(x8, wq8, sa, sbq, b_qkv,
                                                    nullptr, QKV_N, 1,
                                                    qh, ql, kh, kl, vh, vl);
    }
    // 5) HMMA flash attention -> fp32 g_attn
    {
        dim3 grid(16, BATCH * NHEADS);
        attn_mma_kernel<<<grid, 256, ATTN_SMEM>>>(qh, ql, kh, kl, vh, vl, attn);
    }
    // 6) quantize attention output
    quant_act_kernel<<<MROWS, 256>>>(attn, x8, sa);
    // 7) int8 output projection (mode 0)
    {
        dim3 grid(HID / BN8, MROWS / BM8);
        imma_gemm_kernel<<<grid, 256, GEMM8_SMEM>>>(x8, wo8, sa, sbo, b_out,
                                                    out, HID, 0,
                                                    nullptr, nullptr, nullptr,
                                                    nullptr, nullptr, nullptr);
    }
}

// round 8
// speedup vs baseline: 1.7732x; 1.7732x over previous
#include <cuda_runtime.h>
#include <cuda_fp16.h>
#include <cstdint>
#include <math.h>

// Problem constants
#define BATCH   2
#define SEQ     2048
#define HID     1024
#define NHEADS  16
#define HD      64
#define QKV_N   3072
#define MROWS   4096
#define KS      3072          // stacked K = 3*1024 (fp16 limbs)

#define QSCALE  0.18033688f   // 0.125 * log2(e)

// ---------------- scratch (device globals; no allocations allowed) ----------
__device__ __half g_as[(size_t)MROWS * KS];            // stacked activations [ah|al|ah]
__device__ __half g_wqkv_s[(size_t)QKV_N * KS];        // stacked W^T [bh|bh|bl]
__device__ __half g_wout_s[(size_t)HID * KS];
// Head-major fp16 hi/lo Q/K/V: [b*16+h][s][64]
#define HM_ELEMS ((size_t)BATCH * NHEADS * SEQ * HD)
__device__ __half g_qh[HM_ELEMS], g_ql[HM_ELEMS];
__device__ __half g_kh[HM_ELEMS], g_kl[HM_ELEMS];
__device__ __half g_vh[HM_ELEMS], g_vl[HM_ELEMS];

// ---------------- PTX helpers (base ISA only) ----------------
__device__ __forceinline__ uint32_t smem_u32(const void* p) {
    uint32_t a;
    asm("{ .reg .u64 t; cvta.to.shared.u64 t, %1; cvt.u32.u64 %0, t; }" : "=r"(a) : "l"(p));
    return a;
}

__device__ __forceinline__ void cp_async16(uint32_t s, const void* g) {
    asm volatile("cp.async.cg.shared.global [%0], [%1], 16;" :: "r"(s), "l"(g) : "memory");
}
#define CP_COMMIT() asm volatile("cp.async.commit_group;" ::: "memory")
#define CP_WAIT1()  asm volatile("cp.async.wait_group 1;"  ::: "memory")

#define LDSM_X4(R0, R1, R2, R3, ADDR)                                          \
    asm volatile("ldmatrix.sync.aligned.m8n8.x4.shared.b16 {%0,%1,%2,%3}, [%4];" \
                 : "=r"(R0), "=r"(R1), "=r"(R2), "=r"(R3) : "r"(ADDR))

#define LDSM_X4T(R0, R1, R2, R3, ADDR)                                         \
    asm volatile("ldmatrix.sync.aligned.m8n8.x4.trans.shared.b16 {%0,%1,%2,%3}, [%4];" \
                 : "=r"(R0), "=r"(R1), "=r"(R2), "=r"(R3) : "r"(ADDR))

// fp16 inputs, f32 accumulate (main pass)
#define MMAF32(D, A, B0, B1)                                                   \
    asm volatile("mma.sync.aligned.m16n8k16.row.col.f32.f16.f16.f32 "          \
                 "{%0,%1,%2,%3},{%4,%5,%6,%7},{%8,%9},{%0,%1,%2,%3};"          \
                 : "+f"((D)[0]), "+f"((D)[1]), "+f"((D)[2]), "+f"((D)[3])      \
                 : "r"((A)[0]), "r"((A)[1]), "r"((A)[2]), "r"((A)[3]),         \
                   "r"(B0), "r"(B1))

// fp16 inputs, f16 accumulate (cross passes; values ~2^-11 of main)
#define MMAF16(D, A, B0, B1)                                                   \
    asm volatile("mma.sync.aligned.m16n8k16.row.col.f16.f16.f16.f16 "          \
                 "{%0,%1},{%2,%3,%4,%5},{%6,%7},{%0,%1};"                      \
                 : "+r"((D)[0]), "+r"((D)[1])                                  \
                 : "r"((A)[0]), "r"((A)[1]), "r"((A)[2]), "r"((A)[3]),         \
                   "r"(B0), "r"(B1))

// Fast exp2 on FMA/ALU pipes (no MUFU). rel err ~1e-7.
__device__ __forceinline__ float fexp2(float x) {
    x = fmaxf(x, -125.0f);
    int   n  = __float2int_rn(x);
    float f  = x - (float)n;
    float p  = 1.535336188319500e-4f;
    p = fmaf(p, f, 1.339887440266574e-3f);
    p = fmaf(p, f, 9.618437357674640e-3f);
    p = fmaf(p, f, 5.550332471162809e-2f);
    p = fmaf(p, f, 2.402264791363012e-1f);
    p = fmaf(p, f, 6.931472028550421e-1f);
    p = fmaf(p, f, 1.0f);
    return __int_as_float(__float_as_int(p) + (n << 23));
}

__device__ __forceinline__ uint32_t pack2h(__half a, __half b) {
    __half2 t;
    t.x = a; t.y = b;
    return *reinterpret_cast<uint32_t*>(&t);
}

// ---------------------------------------------------------------------------
// Conversion: fp32 activations [R,1024] -> stacked fp16 [R,3072] = [ah|al|ah]
// ---------------------------------------------------------------------------
__global__ __launch_bounds__(256) void convert_act_kernel(
    const float* __restrict__ in, __half* __restrict__ out, int R)
{
    int idx = blockIdx.x * 256 + threadIdx.x;
    int total = R * 1024;
    if (idx >= total) return;
    int m = idx >> 10;
    int k = idx & 1023;
    float v = in[idx];
    __half h = __float2half(v);
    __half l = __float2half(v - __half2float(h));
    size_t o = (size_t)m * KS + k;
    out[o]        = h;
    out[o + 1024] = l;
    out[o + 2048] = h;
}

// ---------------------------------------------------------------------------
// Conversion + transpose: W fp32 [K=1024, N] -> stacked fp16 [N,3072]=[bh|bh|bl]
// ---------------------------------------------------------------------------
__global__ __launch_bounds__(1024) void convert_w_kernel(
    const float* __restrict__ w, __half* __restrict__ out, int N)
{
    __shared__ float tile[32][33];
    int tx = threadIdx.x & 31;
    int ty = threadIdx.x >> 5;
    int gn = blockIdx.x * 32;
    int gk = blockIdx.y * 32;
    tile[ty][tx] = w[(size_t)(gk + ty) * N + gn + tx];
    __syncthreads();
    float v = tile[tx][ty];
    __half h = __float2half(v);
    __half l = __float2half(v - __half2float(h));
    size_t o = (size_t)(gn + ty) * KS + gk + tx;
    out[o]        = h;
    out[o + 1024] = h;
    out[o + 2048] = l;
}

// ---------------------------------------------------------------------------
// HMMA GEMM: C[4096,N] = As[4096,3072] @ Bs[N,3072]^T + bias.
// CTA tile 128x64, 256 threads (8 warps, 4x2), warp tile 32x32.
// Phase 1 (iters 0-15,  ah*bh): f32 accumulate.
// Phase 2 (iters 16-47, al*bh + ah*bl): f16 accumulate, folded at end.
// mode 0: fp32 C out.  mode 1: QKV epilogue -> fp16 hi/lo head-major Q/K/V.
// ---------------------------------------------------------------------------
#define BM 128
#define BN 64
#define BK 64
#define NKITER (KS / BK)                   // 48
#define NPH1   16                          // iters of the f32-acc main phase
#define A_BYTES (BM * 128)                 // 16 KB
#define B_BYTES (BN * 128)                 // 8 KB
#define STAGE_BYTES (A_BYTES + B_BYTES)    // 24 KB
#define GEMM_SMEM (3 * STAGE_BYTES + 128)

__global__ __launch_bounds__(256, 2) void mma_gemm_kernel(
    const __half* __restrict__ As, const __half* __restrict__ Bs,
    const float* __restrict__ bias, float* __restrict__ C, int N, int mode,
    __half* __restrict__ qh, __half* __restrict__ ql,
    __half* __restrict__ kh, __half* __restrict__ kl,
    __half* __restrict__ vh, __half* __restrict__ vl)
{
    extern __shared__ char dsmem[];
    const uint32_t smem_base = (smem_u32(dsmem) + 127u) & ~127u;

    const int tid  = threadIdx.x;
    const int wid  = tid >> 5;
    const int lane = tid & 31;
    const int wm   = wid >> 1;     // 0..3 (32-row slab)
    const int wn   = wid & 1;      // 0..1 (32-col slab)

    const int block_row = blockIdx.y * BM;
    const int block_col = blockIdx.x * BN;

    const __half* Abase = As + (size_t)block_row * KS;
    const __half* Bbase = Bs + (size_t)block_col * KS;

    auto load_stage = [&](int stage, int kc) {
        const uint32_t sA = smem_base + stage * STAGE_BYTES;
        const uint32_t sB = sA + A_BYTES;
#pragma unroll
        for (int i = 0; i < 4; i++) {       // A: 1024 16B segs
            const int s   = i * 256 + tid;
            const int row = s >> 3;
            const int ch  = s & 7;
            const uint32_t sw = (uint32_t)(ch * 16) ^ (uint32_t)((row & 7) << 4);
            cp_async16(sA + row * 128 + sw, Abase + (size_t)row * KS + kc + ch * 8);
        }
#pragma unroll
        for (int i = 0; i < 2; i++) {       // B: 512 16B segs
            const int s   = i * 256 + tid;
            const int row = s >> 3;
            const int ch  = s & 7;
            const uint32_t sw = (uint32_t)(ch * 16) ^ (uint32_t)((row & 7) << 4);
            cp_async16(sB + row * 128 + sw, Bbase + (size_t)row * KS + kc + ch * 8);
        }
        CP_COMMIT();
    };

    float    facc[2][4][4];
    uint32_t hacc[2][4][2];
#pragma unroll
    for (int mt = 0; mt < 2; mt++)
#pragma unroll
        for (int nt = 0; nt < 4; nt++) {
#pragma unroll
            for (int r = 0; r < 4; r++) facc[mt][nt][r] = 0.0f;
            hacc[mt][nt][0] = 0u; hacc[mt][nt][1] = 0u;
        }

    load_stage(0, 0);
    load_stage(1, BK);

    const int lrow  = lane & 15;
    const int kseg  = (lane >> 4) * 16;
    const uint32_t arow_off = (uint32_t)(wm * 32 + lrow) * 128;
    const uint32_t brow_off = (uint32_t)(wn * 32 + lrow) * 128;
    const uint32_t aswz = (uint32_t)((lrow & 7) << 4);

    // ---- phase 1: main term ah*bh, f32 accumulate ----
    for (int it = 0; it < NPH1; it++) {
        CP_WAIT1();
        __syncthreads();
        load_stage((it + 2) % 3, (it + 2) * BK);
        const uint32_t sA = smem_base + (it % 3) * STAGE_BYTES;
        const uint32_t sB = sA + A_BYTES;
#pragma unroll
        for (int kt = 0; kt < 4; kt++) {
            const uint32_t koff = ((uint32_t)(kt * 32 + kseg)) ^ aswz;
            uint32_t a[2][4], bb[2][4];
#pragma unroll
            for (int mt = 0; mt < 2; mt++)
                LDSM_X4(a[mt][0], a[mt][1], a[mt][2], a[mt][3],
                        sA + arow_off + (uint32_t)(mt * 16 * 128) + koff);
#pragma unroll
            for (int pr = 0; pr < 2; pr++)
                LDSM_X4(bb[pr][0], bb[pr][1], bb[pr][2], bb[pr][3],
                        sB + brow_off + (uint32_t)(pr * 16 * 128) + koff);
#pragma unroll
            for (int mt = 0; mt < 2; mt++)
#pragma unroll
                for (int nt = 0; nt < 4; nt++) {
                    const int pr = nt >> 1, sub = nt & 1;
                    MMAF32(facc[mt][nt], a[mt], bb[pr][sub], bb[pr][sub + 2]);
                }
        }
        __syncthreads();
    }

    // ---- phase 2: cross terms al*bh + ah*bl, f16 accumulate ----
    for (int it = NPH1; it < NKITER; it++) {
        CP_WAIT1();
        __syncthreads();
        if (it + 2 < NKITER) load_stage((it + 2) % 3, (it + 2) * BK);
        else                 CP_COMMIT();
        const uint32_t sA = smem_base + (it % 3) * STAGE_BYTES;
        const uint32_t sB = sA + A_BYTES;
#pragma unroll
        for (int kt = 0; kt < 4; kt++) {
            const uint32_t koff = ((uint32_t)(kt * 32 + kseg)) ^ aswz;
            uint32_t a[2][4], bb[2][4];
#pragma unroll
            for (int mt = 0; mt < 2; mt++)
                LDSM_X4(a[mt][0], a[mt][1], a[mt][2], a[mt][3],
                        sA + arow_off + (uint32_t)(mt * 16 * 128) + koff);
#pragma unroll
            for (int pr = 0; pr < 2; pr++)
                LDSM_X4(bb[pr][0], bb[pr][1], bb[pr][2], bb[pr][3],
                        sB + brow_off + (uint32_t)(pr * 16 * 128) + koff);
#pragma unroll
            for (int mt = 0; mt < 2; mt++)
#pragma unroll
                for (int nt = 0; nt < 4; nt++) {
                    const int pr = nt >> 1, sub = nt & 1;
                    MMAF16(hacc[mt][nt], a[mt], bb[pr][sub], bb[pr][sub + 2]);
                }
        }
        __syncthreads();
    }

    const int rbase = block_row + wm * 32 + (lane >> 2);
    const int cbase = block_col + wn * 32 + (lane & 3) * 2;

#pragma unroll
    for (int mt = 0; mt < 2; mt++) {
#pragma unroll
        for (int nt = 0; nt < 4; nt++) {
            const float2 cx01 = __half22float2(*reinterpret_cast<__half2*>(&hacc[mt][nt][0]));
            const float2 cx23 = __half22float2(*reinterpret_cast<__half2*>(&hacc[mt][nt][1]));
            const int col = cbase + nt * 8;
            const float bx = bias[col];
            const float by = bias[col + 1];
            const float r00 = facc[mt][nt][0] + cx01.x + bx;
            const float r01 = facc[mt][nt][1] + cx01.y + by;
            const float r10 = facc[mt][nt][2] + cx23.x + bx;
            const float r11 = facc[mt][nt][3] + cx23.y + by;
            if (mode == 0) {
                const int r0 = rbase + mt * 16;
                float2 o0 = { r00, r01 };
                float2 o1 = { r10, r11 };
                *(float2*)(C + (size_t)r0 * N + col)       = o0;
                *(float2*)(C + (size_t)(r0 + 8) * N + col) = o1;
            } else {
                const int part = col >> 10;          // CTA-uniform (BN=64, head-aligned)
                const int hh   = (col >> 6) & 15;
                const int dd   = col & 63;
                __half* dh = part == 0 ? qh : (part == 1 ? kh : vh);
                __half* dl = part == 0 ? ql : (part == 1 ? kl : vl);
                const float sc = part == 0 ? QSCALE : 1.0f;
#pragma unroll
                for (int rr = 0; rr < 2; rr++) {
                    const int r = rbase + mt * 16 + rr * 8;
                    const float v0 = (rr ? r10 : r00) * sc;
                    const float v1 = (rr ? r11 : r01) * sc;
                    const __half h0 = __float2half(v0);
                    const __half h1 = __float2half(v1);
                    const size_t off =
                        (((size_t)((r >> 11) * 16 + hh)) * SEQ + (r & 2047)) * 64 + dd;
                    *(uint32_t*)(dh + off) = pack2h(h0, h1);
                    *(uint32_t*)(dl + off) =
                        pack2h(__float2half(v0 - __half2float(h0)),
                               __float2half(v1 - __half2float(h1)));
                }
            }
        }
    }
}

// ---------------------------------------------------------------------------
// HMMA causal flash attention, fp16-fed, 3-stage cp.async pipeline.
// One CTA = 128 queries of one (b,h); 8 warps x 16 rows; 64-key tiles.
// Main terms f32-acc; cross terms (ql*kh + qh*kl, pl*vh + ph*vl) f16-acc
// per tile, folded into the f32 state.
// Output written as stacked fp16 [ah|al|ah] rows of g_as.
// smem: QH 16K | QL 16K | 3 stages x {KH,KL,VH,VL 8K each} = 128KB
// ---------------------------------------------------------------------------
#define KV_STAGE_BYTES 32768
#define ATTN_SMEM (32768 + 3 * KV_STAGE_BYTES + 128)

__global__ __launch_bounds__(256) void attn_mma_kernel(
    const __half* __restrict__ qh_g, const __half* __restrict__ ql_g,
    const __half* __restrict__ kh_g, const __half* __restrict__ kl_g,
    const __half* __restrict__ vh_g, const __half* __restrict__ vl_g,
    __half* __restrict__ outs)
{
    extern __shared__ char sm[];
    const uint32_t base = (smem_u32(sm) + 127u) & ~127u;
    const uint32_t sQH = base;
    const uint32_t sQL = base + 16384;
    const uint32_t kvbase = base + 32768;

    const int tid  = threadIdx.x;
    const int lane = tid & 31;
    const int wid  = tid >> 5;
    const int qb   = 15 - (int)blockIdx.x;     // heavy blocks first
    const int bh   = blockIdx.y;
    const int b    = bh >> 4;
    const int h    = bh & 15;
    const size_t hrow = (size_t)bh * SEQ;

    // ---- Q tile cp.async (part of group 0) ----
#pragma unroll
    for (int i = 0; i < 4; i++) {
        const int s   = i * 256 + tid;
        const int row = s >> 3;
        const int ch  = s & 7;
        const uint32_t sw = (uint32_t)(ch * 16) ^ (uint32_t)((row & 7) << 4);
        const size_t gofs = (hrow + qb * 128 + row) * 64 + ch * 8;
        cp_async16(sQH + row * 128 + sw, qh_g + gofs);
        cp_async16(sQL + row * 128 + sw, ql_g + gofs);
    }

    auto load_kv = [&](int stage, int k0) {
        const uint32_t sb = kvbase + stage * KV_STAGE_BYTES;
#pragma unroll
        for (int i = 0; i < 2; i++) {
            const int s   = i * 256 + tid;
            const int row = s >> 3;
            const int ch  = s & 7;
            const uint32_t sw = (uint32_t)(ch * 16) ^ (uint32_t)((row & 7) << 4);
            const uint32_t so = row * 128 + sw;
            const size_t gofs = (hrow + k0 + row) * 64 + ch * 8;
            cp_async16(sb + so,         kh_g + gofs);
            cp_async16(sb + 8192 + so,  kl_g + gofs);
            cp_async16(sb + 16384 + so, vh_g + gofs);
            cp_async16(sb + 24576 + so, vl_g + gofs);
        }
        CP_COMMIT();
    };

    const int nk = (qb + 1) * 2;
    load_kv(0, 0);
    load_kv(1, 64);

    float acc_o[8][4];
#pragma unroll
    for (int nt = 0; nt < 8; nt++)
#pragma unroll
        for (int r = 0; r < 4; r++) acc_o[nt][r] = 0.0f;
    float m0 = -1e30f, m1 = -1e30f, l0 = 0.0f, l1 = 0.0f;

    const int r0      = lane >> 2;
    const int qrow_w  = qb * 128 + wid * 16;
    const int qg0     = qrow_w + r0;

    const int a_r = wid * 16 + (lane & 15);
    const int a_c = (lane >> 4) * 16;
    const uint32_t a_row_off = (uint32_t)(a_r * 128);
    const uint32_t a_sw = (uint32_t)((a_r & 7) << 4);
    const int g      = lane >> 3;
    const int br_off = lane & 7;

    for (int t = 0; t < nk; t++) {
        const int k0 = t * 64;
        CP_WAIT1();
        __syncthreads();
        if (t + 2 < nk) load_kv((t + 2) % 3, (t + 2) * 64);
        else            CP_COMMIT();

        const uint32_t st  = kvbase + (t % 3) * KV_STAGE_BYTES;
        const uint32_t sKH = st;
        const uint32_t sKL = st + 8192;
        const uint32_t sVH = st + 16384;
        const uint32_t sVL = st + 24576;

        // ---- S = Q K^T: main f32, cross f16 ----
        float s[8][4];
        uint32_t scx[8][2];
#pragma unroll
        for (int nt = 0; nt < 8; nt++) {
#pragma unroll
            for (int r = 0; r < 4; r++) s[nt][r] = 0.0f;
            scx[nt][0] = 0u; scx[nt][1] = 0u;
        }

#pragma unroll
        for (int kc = 0; kc < 4; kc++) {
            uint32_t qhf[4], qlf[4];
            const uint32_t qoff = ((uint32_t)(kc * 32 + a_c)) ^ a_sw;
            LDSM_X4(qhf[0], qhf[1], qhf[2], qhf[3], sQH + a_row_off + qoff);
            LDSM_X4(qlf[0], qlf[1], qlf[2], qlf[3], sQL + a_row_off + qoff);
#pragma unroll
            for (int np = 0; np < 4; np++) {
                const int brow = np * 16 + ((g & 2) << 2) + br_off;
                const uint32_t boff = ((uint32_t)(kc * 32 + ((g & 1) << 4)))
                                    ^ (uint32_t)((brow & 7) << 4);
                const uint32_t rb = (uint32_t)(brow * 128) + boff;
                uint32_t kh0, kh1, kh2, kh3, kl0, kl1, kl2, kl3;
                LDSM_X4(kh0, kh1, kh2, kh3, sKH + rb);
                LDSM_X4(kl0, kl1, kl2, kl3, sKL + rb);
                MMAF32(s[2 * np],     qhf, kh0, kh1);
                MMAF32(s[2 * np + 1], qhf, kh2, kh3);
                MMAF16(scx[2 * np],     qlf, kh0, kh1);
                MMAF16(scx[2 * np + 1], qlf, kh2, kh3);
                MMAF16(scx[2 * np],     qhf, kl0, kl1);
                MMAF16(scx[2 * np + 1], qhf, kl2, kl3);
            }
        }
        // fold cross terms
#pragma unroll
        for (int nt = 0; nt < 8; nt++) {
            const float2 cA = __half22float2(*reinterpret_cast<__half2*>(&scx[nt][0]));
            const float2 cB = __half22float2(*reinterpret_cast<__half2*>(&scx[nt][1]));
            s[nt][0] += cA.x; s[nt][1] += cA.y;
            s[nt][2] += cB.x; s[nt][3] += cB.y;
        }

        // ---- causal mask ----
        if (k0 + 63 > qrow_w) {
#pragma unroll
            for (int nt = 0; nt < 8; nt++) {
                const int kg0 = k0 + nt * 8 + 2 * (lane & 3);
                if (kg0     > qg0)     s[nt][0] = -1e30f;
                if (kg0 + 1 > qg0)     s[nt][1] = -1e30f;
                if (kg0     > qg0 + 8) s[nt][2] = -1e30f;
                if (kg0 + 1 > qg0 + 8) s[nt][3] = -1e30f;
            }
        }

        // ---- online softmax (base-2) ----
        float rx0 = -1e30f, rx1 = -1e30f;
#pragma unroll
        for (int nt = 0; nt < 8; nt++) {
            rx0 = fmaxf(rx0, fmaxf(s[nt][0], s[nt][1]));
            rx1 = fmaxf(rx1, fmaxf(s[nt][2], s[nt][3]));
        }
        rx0 = fmaxf(rx0, __shfl_xor_sync(0xffffffffu, rx0, 1));
        rx0 = fmaxf(rx0, __shfl_xor_sync(0xffffffffu, rx0, 2));
        rx1 = fmaxf(rx1, __shfl_xor_sync(0xffffffffu, rx1, 1));
        rx1 = fmaxf(rx1, __shfl_xor_sync(0xffffffffu, rx1, 2));
        const float mn0 = fmaxf(m0, rx0);
        const float mn1 = fmaxf(m1, rx1);
        const float sc0 = fexp2(m0 - mn0);
        const float sc1 = fexp2(m1 - mn1);
        m0 = mn0; m1 = mn1;
        l0 *= sc0; l1 *= sc1;
#pragma unroll
        for (int nt = 0; nt < 8; nt++) {
            acc_o[nt][0] *= sc0; acc_o[nt][1] *= sc0;
            acc_o[nt][2] *= sc1; acc_o[nt][3] *= sc1;
        }

        uint32_t ph[4][4], pl[4][4];
#pragma unroll
        for (int nt = 0; nt < 8; nt++) {
            const float p0 = fexp2(s[nt][0] - m0);
            const float p1 = fexp2(s[nt][1] - m0);
            const float p2 = fexp2(s[nt][2] - m1);
            const float p3 = fexp2(s[nt][3] - m1);
            l0 += p0 + p1;
            l1 += p2 + p3;
            const __half h0 = __float2half(p0);
            const __half h1 = __float2half(p1);
            const __half h2 = __float2half(p2);
            const __half h3 = __float2half(p3);
            const int kc = nt >> 1;
            const int rr = (nt & 1) * 2;
            ph[kc][rr]     = pack2h(h0, h1);
            ph[kc][rr + 1] = pack2h(h2, h3);
            pl[kc][rr]     = pack2h(__float2half(p0 - __half2float(h0)),
                                    __float2half(p1 - __half2float(h1)));
            pl[kc][rr + 1] = pack2h(__float2half(p2 - __half2float(h2)),
                                    __float2half(p3 - __half2float(h3)));
        }

        // ---- O += P V: main f32, cross f16 (per-tile, folded) ----
        uint32_t ocx[8][2];
#pragma unroll
        for (int nt = 0; nt < 8; nt++) { ocx[nt][0] = 0u; ocx[nt][1] = 0u; }
#pragma unroll
        for (int kc = 0; kc < 4; kc++) {
#pragma unroll
            for (int np = 0; np < 4; np++) {
                const int vrow = kc * 16 + ((g & 1) << 3) + br_off;
                const uint32_t voff = ((uint32_t)(np * 32 + ((g & 2) << 3)))
                                    ^ (uint32_t)((vrow & 7) << 4);
                const uint32_t rv = (uint32_t)(vrow * 128) + voff;
                uint32_t vh0, vh1, vh2, vh3, vl0, vl1, vl2, vl3;
                LDSM_X4T(vh0, vh1, vh2, vh3, sVH + rv);
                LDSM_X4T(vl0, vl1, vl2, vl3, sVL + rv);
                MMAF32(acc_o[2 * np],     ph[kc], vh0, vh1);
                MMAF32(acc_o[2 * np + 1], ph[kc], vh2, vh3);
                MMAF16(ocx[2 * np],     pl[kc], vh0, vh1);
                MMAF16(ocx[2 * np + 1], pl[kc], vh2, vh3);
                MMAF16(ocx[2 * np],     ph[kc], vl0, vl1);
                MMAF16(ocx[2 * np + 1], ph[kc], vl2, vl3);
            }
        }
#pragma unroll
        for (int nt = 0; nt < 8; nt++) {
            const float2 cA = __half22float2(*reinterpret_cast<__half2*>(&ocx[nt][0]));
            const float2 cB = __half22float2(*reinterpret_cast<__half2*>(&ocx[nt][1]));
            acc_o[nt][0] += cA.x; acc_o[nt][1] += cA.y;
            acc_o[nt][2] += cB.x; acc_o[nt][3] += cB.y;
        }
    }

    // ---- epilogue: normalize, write stacked fp16 [ah|al|ah] rows of g_as ----
    l0 += __shfl_xor_sync(0xffffffffu, l0, 1);
    l0 += __shfl_xor_sync(0xffffffffu, l0, 2);
    l1 += __shfl_xor_sync(0xffffffffu, l1, 1);
    l1 += __shfl_xor_sync(0xffffffffu, l1, 2);
    const float inv0 = 1.0f / l0;
    const float inv1 = 1.0f / l1;

    const size_t row0 = (size_t)(b * SEQ + qg0) * KS;
    const size_t row1 = row0 + 8 * KS;
    const int colbase = h * HD + 2 * (lane & 3);
#pragma unroll
    for (int nt = 0; nt < 8; nt++) {
        const int col = colbase + nt * 8;
        const float v0 = acc_o[nt][0] * inv0;
        const float v1 = acc_o[nt][1] * inv0;
        const float v2 = acc_o[nt][2] * inv1;
        const float v3 = acc_o[nt][3] * inv1;
        const __half h0 = __float2half(v0);
        const __half h1 = __float2half(v1);
        const __half h2 = __float2half(v2);
        const __half h3 = __float2half(v3);
        const uint32_t hi01 = pack2h(h0, h1);
        const uint32_t lo01 = pack2h(__float2half(v0 - __half2float(h0)),
                                     __float2half(v1 - __half2float(h1)));
        const uint32_t hi23 = pack2h(h2, h3);
        const uint32_t lo23 = pack2h(__float2half(v2 - __half2float(h2)),
                                     __float2half(v3 - __half2float(h3)));
        *(uint32_t*)(outs + row0 + col)        = hi01;
        *(uint32_t*)(outs + row0 + col + 1024) = lo01;
        *(uint32_t*)(outs + row0 + col + 2048) = hi01;
        *(uint32_t*)(outs + row1 + col)        = hi23;
        *(uint32_t*)(outs + row1 + col + 1024) = lo23;
        *(uint32_t*)(outs + row1 + col + 2048) = hi23;
    }
}

// ---------------------------------------------------------------------------
extern "C" void kernel_launch(void* const* d_in, const int* in_sizes, int n_in,
                              void* d_out, int out_size)
{
    const float* x     = (const float*)d_in[0];
    const float* w_qkv = (const float*)d_in[1];
    const float* b_qkv = (const float*)d_in[2];
    const float* w_out = (const float*)d_in[3];
    const float* b_out = (const float*)d_in[4];
    float* out = (float*)d_out;

    __half *as, *wqkvs, *wouts, *qh, *ql, *kh, *kl, *vh, *vl;
    cudaGetSymbolAddress((void**)&as,    g_as);
    cudaGetSymbolAddress((void**)&wqkvs, g_wqkv_s);
    cudaGetSymbolAddress((void**)&wouts, g_wout_s);
    cudaGetSymbolAddress((void**)&qh, g_qh);
    cudaGetSymbolAddress((void**)&ql, g_ql);
    cudaGetSymbolAddress((void**)&kh, g_kh);
    cudaGetSymbolAddress((void**)&kl, g_kl);
    cudaGetSymbolAddress((void**)&vh, g_vh);
    cudaGetSymbolAddress((void**)&vl, g_vl);

    cudaFuncSetAttribute(mma_gemm_kernel,
                         cudaFuncAttributeMaxDynamicSharedMemorySize, GEMM_SMEM);
    cudaFuncSetAttribute(attn_mma_kernel,
                         cudaFuncAttributeMaxDynamicSharedMemorySize, ATTN_SMEM);

    // 1) Convert weights (transpose + fp16 hi/lo split)
    {
        dim3 grid(QKV_N / 32, HID / 32);
        convert_w_kernel<<<grid, 1024>>>(w_qkv, wqkvs, QKV_N);
    }
    {
        dim3 grid(HID / 32, HID / 32);
        convert_w_kernel<<<grid, 1024>>>(w_out, wouts, HID);
    }
    // 2) Convert x
    convert_act_kernel<<<(MROWS * 1024 + 255) / 256, 256>>>(x, as, MROWS);
    // 3) QKV projection -> head-major fp16 hi/lo Q/K/V (mode 1)
    {
        dim3 grid(QKV_N / BN, MROWS / BM);
        mma_gemm_kernel<<<grid, 256, GEMM_SMEM>>>(as, wqkvs, b_qkv, nullptr,
                                                  QKV_N, 1,
                                                  qh, ql, kh, kl, vh, vl);
    }
    // 4) HMMA flash attention -> stacked fp16 g_as
    {
        dim3 grid(16, BATCH * NHEADS);
        attn_mma_kernel<<<grid, 256, ATTN_SMEM>>>(qh, ql, kh, kl, vh, vl, as);
    }
    // 5) Output projection (mode 0)
    {
        dim3 grid(HID / BN, MROWS / BM);
        mma_gemm_kernel<<<grid, 256, GEMM_SMEM>>>(as, wouts, b_out, out,
                                                  HID, 0,
                                                  nullptr, nullptr, nullptr,
                                                  nullptr, nullptr, nullptr);
    }
}

// round 9
// speedup vs baseline: 2.3753x; 1.3396x over previous
#include <cuda_runtime.h>
#include <cuda_fp16.h>
#include <cstdint>
#include <math.h>

// Problem constants
#define BATCH   2
#define SEQ     2048
#define HID     1024
#define NHEADS  16
#define HD      64
#define QKV_N   3072
#define MROWS   4096
#define KS      2048          // stacked K = 2*1024 (2-pass: B split, A single limb)

#define QSCALE  0.18033688f   // 0.125 * log2(e)

// ---------------- scratch (device globals; no allocations allowed) ----------
__device__ __half g_as[(size_t)MROWS * KS];            // stacked activations [a|a]
__device__ __half g_wqkv_s[(size_t)QKV_N * KS];        // stacked W^T [bh|bl]
__device__ __half g_wout_s[(size_t)HID * KS];
// Head-major fp16 Q (single limb) and hi/lo K/V: [b*16+h][s][64]
#define HM_ELEMS ((size_t)BATCH * NHEADS * SEQ * HD)
__device__ __half g_qh[HM_ELEMS];
__device__ __half g_kh[HM_ELEMS], g_kl[HM_ELEMS];
__device__ __half g_vh[HM_ELEMS], g_vl[HM_ELEMS];

// ---------------- PTX helpers (base ISA only) ----------------
__device__ __forceinline__ uint32_t smem_u32(const void* p) {
    uint32_t a;
    asm("{ .reg .u64 t; cvta.to.shared.u64 t, %1; cvt.u32.u64 %0, t; }" : "=r"(a) : "l"(p));
    return a;
}

__device__ __forceinline__ void cp_async16(uint32_t s, const void* g) {
    asm volatile("cp.async.cg.shared.global [%0], [%1], 16;" :: "r"(s), "l"(g) : "memory");
}
#define CP_COMMIT() asm volatile("cp.async.commit_group;" ::: "memory")
#define CP_WAIT1()  asm volatile("cp.async.wait_group 1;"  ::: "memory")

#define LDSM_X4(R0, R1, R2, R3, ADDR)                                          \
    asm volatile("ldmatrix.sync.aligned.m8n8.x4.shared.b16 {%0,%1,%2,%3}, [%4];" \
                 : "=r"(R0), "=r"(R1), "=r"(R2), "=r"(R3) : "r"(ADDR))

#define LDSM_X4T(R0, R1, R2, R3, ADDR)                                         \
    asm volatile("ldmatrix.sync.aligned.m8n8.x4.trans.shared.b16 {%0,%1,%2,%3}, [%4];" \
                 : "=r"(R0), "=r"(R1), "=r"(R2), "=r"(R3) : "r"(ADDR))

// fp16 inputs, f32 accumulate (main pass)
#define MMAF32(D, A, B0, B1)                                                   \
    asm volatile("mma.sync.aligned.m16n8k16.row.col.f32.f16.f16.f32 "          \
                 "{%0,%1,%2,%3},{%4,%5,%6,%7},{%8,%9},{%0,%1,%2,%3};"          \
                 : "+f"((D)[0]), "+f"((D)[1]), "+f"((D)[2]), "+f"((D)[3])      \
                 : "r"((A)[0]), "r"((A)[1]), "r"((A)[2]), "r"((A)[3]),         \
                   "r"(B0), "r"(B1))

// fp16 inputs, f16 accumulate (cross pass; values ~2^-11 of main)
#define MMAF16(D, A, B0, B1)                                                   \
    asm volatile("mma.sync.aligned.m16n8k16.row.col.f16.f16.f16.f16 "          \
                 "{%0,%1},{%2,%3,%4,%5},{%6,%7},{%0,%1};"                      \
                 : "+r"((D)[0]), "+r"((D)[1])                                  \
                 : "r"((A)[0]), "r"((A)[1]), "r"((A)[2]), "r"((A)[3]),         \
                   "r"(B0), "r"(B1))

// Fast exp2 on FMA/ALU pipes (no MUFU). rel err ~1e-7.
__device__ __forceinline__ float fexp2(float x) {
    x = fmaxf(x, -125.0f);
    int   n  = __float2int_rn(x);
    float f  = x - (float)n;
    float p  = 1.535336188319500e-4f;
    p = fmaf(p, f, 1.339887440266574e-3f);
    p = fmaf(p, f, 9.618437357674640e-3f);
    p = fmaf(p, f, 5.550332471162809e-2f);
    p = fmaf(p, f, 2.402264791363012e-1f);
    p = fmaf(p, f, 6.931472028550421e-1f);
    p = fmaf(p, f, 1.0f);
    return __int_as_float(__float_as_int(p) + (n << 23));
}

__device__ __forceinline__ uint32_t pack2h(__half a, __half b) {
    __half2 t;
    t.x = a; t.y = b;
    return *reinterpret_cast<uint32_t*>(&t);
}

// ---------------------------------------------------------------------------
// Conversion: fp32 activations [R,1024] -> stacked fp16 [R,2048] = [a | a]
// ---------------------------------------------------------------------------
__global__ __launch_bounds__(256) void convert_act_kernel(
    const float* __restrict__ in, __half* __restrict__ out, int R)
{
    int idx = blockIdx.x * 256 + threadIdx.x;
    int total = R * 1024;
    if (idx >= total) return;
    int m = idx >> 10;
    int k = idx & 1023;
    __half h = __float2half(in[idx]);
    size_t o = (size_t)m * KS + k;
    out[o]        = h;
    out[o + 1024] = h;
}

// ---------------------------------------------------------------------------
// Conversion + transpose: W fp32 [K=1024, N] -> stacked fp16 [N,2048]=[bh|bl]
// ---------------------------------------------------------------------------
__global__ __launch_bounds__(1024) void convert_w_kernel(
    const float* __restrict__ w, __half* __restrict__ out, int N)
{
    __shared__ float tile[32][33];
    int tx = threadIdx.x & 31;
    int ty = threadIdx.x >> 5;
    int gn = blockIdx.x * 32;
    int gk = blockIdx.y * 32;
    tile[ty][tx] = w[(size_t)(gk + ty) * N + gn + tx];
    __syncthreads();
    float v = tile[tx][ty];
    __half h = __float2half(v);
    __half l = __float2half(v - __half2float(h));
    size_t o = (size_t)(gn + ty) * KS + gk + tx;
    out[o]        = h;
    out[o + 1024] = l;
}

// ---------------------------------------------------------------------------
// HMMA GEMM: C[4096,N] = As[4096,2048] @ Bs[N,2048]^T + bias.
// CTA tile 128x64, 256 threads (8 warps, 4x2), warp tile 32x32.
// Phase 1 (iters 0-15,  a*bh): f32 accumulate.
// Phase 2 (iters 16-31, a*bl): f16 accumulate, folded at end.
// mode 0: fp32 C out.  mode 1: QKV epilogue -> fp16 Q (single) / K,V hi-lo.
// ---------------------------------------------------------------------------
#define BM 128
#define BN 64
#define BK 64
#define NKITER (KS / BK)                   // 32
#define NPH1   16                          // iters of the f32-acc main phase
#define A_BYTES (BM * 128)                 // 16 KB
#define B_BYTES (BN * 128)                 // 8 KB
#define STAGE_BYTES (A_BYTES + B_BYTES)    // 24 KB
#define GEMM_SMEM (3 * STAGE_BYTES + 128)

__global__ __launch_bounds__(256, 2) void mma_gemm_kernel(
    const __half* __restrict__ As, const __half* __restrict__ Bs,
    const float* __restrict__ bias, float* __restrict__ C, int N, int mode,
    __half* __restrict__ qh,
    __half* __restrict__ kh, __half* __restrict__ kl,
    __half* __restrict__ vh, __half* __restrict__ vl)
{
    extern __shared__ char dsmem[];
    const uint32_t smem_base = (smem_u32(dsmem) + 127u) & ~127u;

    const int tid  = threadIdx.x;
    const int wid  = tid >> 5;
    const int lane = tid & 31;
    const int wm   = wid >> 1;     // 0..3 (32-row slab)
    const int wn   = wid & 1;      // 0..1 (32-col slab)

    const int block_row = blockIdx.y * BM;
    const int block_col = blockIdx.x * BN;

    const __half* Abase = As + (size_t)block_row * KS;
    const __half* Bbase = Bs + (size_t)block_col * KS;

    auto load_stage = [&](int stage, int kc) {
        const uint32_t sA = smem_base + stage * STAGE_BYTES;
        const uint32_t sB = sA + A_BYTES;
#pragma unroll
        for (int i = 0; i < 4; i++) {       // A: 1024 16B segs
            const int s   = i * 256 + tid;
            const int row = s >> 3;
            const int ch  = s & 7;
            const uint32_t sw = (uint32_t)(ch * 16) ^ (uint32_t)((row & 7) << 4);
            cp_async16(sA + row * 128 + sw, Abase + (size_t)row * KS + kc + ch * 8);
        }
#pragma unroll
        for (int i = 0; i < 2; i++) {       // B: 512 16B segs
            const int s   = i * 256 + tid;
            const int row = s >> 3;
            const int ch  = s & 7;
            const uint32_t sw = (uint32_t)(ch * 16) ^ (uint32_t)((row & 7) << 4);
            cp_async16(sB + row * 128 + sw, Bbase + (size_t)row * KS + kc + ch * 8);
        }
        CP_COMMIT();
    };

    float    facc[2][4][4];
    uint32_t hacc[2][4][2];
#pragma unroll
    for (int mt = 0; mt < 2; mt++)
#pragma unroll
        for (int nt = 0; nt < 4; nt++) {
#pragma unroll
            for (int r = 0; r < 4; r++) facc[mt][nt][r] = 0.0f;
            hacc[mt][nt][0] = 0u; hacc[mt][nt][1] = 0u;
        }

    load_stage(0, 0);
    load_stage(1, BK);

    const int lrow  = lane & 15;
    const int kseg  = (lane >> 4) * 16;
    const uint32_t arow_off = (uint32_t)(wm * 32 + lrow) * 128;
    const uint32_t brow_off = (uint32_t)(wn * 32 + lrow) * 128;
    const uint32_t aswz = (uint32_t)((lrow & 7) << 4);

    // ---- phase 1: main term a*bh, f32 accumulate ----
    for (int it = 0; it < NPH1; it++) {
        CP_WAIT1();
        __syncthreads();
        load_stage((it + 2) % 3, (it + 2) * BK);
        const uint32_t sA = smem_base + (it % 3) * STAGE_BYTES;
        const uint32_t sB = sA + A_BYTES;
#pragma unroll
        for (int kt = 0; kt < 4; kt++) {
            const uint32_t koff = ((uint32_t)(kt * 32 + kseg)) ^ aswz;
            uint32_t a[2][4], bb[2][4];
#pragma unroll
            for (int mt = 0; mt < 2; mt++)
                LDSM_X4(a[mt][0], a[mt][1], a[mt][2], a[mt][3],
                        sA + arow_off + (uint32_t)(mt * 16 * 128) + koff);
#pragma unroll
            for (int pr = 0; pr < 2; pr++)
                LDSM_X4(bb[pr][0], bb[pr][1], bb[pr][2], bb[pr][3],
                        sB + brow_off + (uint32_t)(pr * 16 * 128) + koff);
#pragma unroll
            for (int mt = 0; mt < 2; mt++)
#pragma unroll
                for (int nt = 0; nt < 4; nt++) {
                    const int pr = nt >> 1, sub = nt & 1;
                    MMAF32(facc[mt][nt], a[mt], bb[pr][sub], bb[pr][sub + 2]);
                }
        }
        __syncthreads();
    }

    // ---- phase 2: cross term a*bl, f16 accumulate ----
    for (int it = NPH1; it < NKITER; it++) {
        CP_WAIT1();
        __syncthreads();
        if (it + 2 < NKITER) load_stage((it + 2) % 3, (it + 2) * BK);
        else                 CP_COMMIT();
        const uint32_t sA = smem_base + (it % 3) * STAGE_BYTES;
        const uint32_t sB = sA + A_BYTES;
#pragma unroll
        for (int kt = 0; kt < 4; kt++) {
            const uint32_t koff = ((uint32_t)(kt * 32 + kseg)) ^ aswz;
            uint32_t a[2][4], bb[2][4];
#pragma unroll
            for (int mt = 0; mt < 2; mt++)
                LDSM_X4(a[mt][0], a[mt][1], a[mt][2], a[mt][3],
                        sA + arow_off + (uint32_t)(mt * 16 * 128) + koff);
#pragma unroll
            for (int pr = 0; pr < 2; pr++)
                LDSM_X4(bb[pr][0], bb[pr][1], bb[pr][2], bb[pr][3],
                        sB + brow_off + (uint32_t)(pr * 16 * 128) + koff);
#pragma unroll
            for (int mt = 0; mt < 2; mt++)
#pragma unroll
                for (int nt = 0; nt < 4; nt++) {
                    const int pr = nt >> 1, sub = nt & 1;
                    MMAF16(hacc[mt][nt], a[mt], bb[pr][sub], bb[pr][sub + 2]);
                }
        }
        __syncthreads();
    }

    const int rbase = block_row + wm * 32 + (lane >> 2);
    const int cbase = block_col + wn * 32 + (lane & 3) * 2;

#pragma unroll
    for (int mt = 0; mt < 2; mt++) {
#pragma unroll
        for (int nt = 0; nt < 4; nt++) {
            const float2 cx01 = __half22float2(*reinterpret_cast<__half2*>(&hacc[mt][nt][0]));
            const float2 cx23 = __half22float2(*reinterpret_cast<__half2*>(&hacc[mt][nt][1]));
            const int col = cbase + nt * 8;
            const float bx = bias[col];
            const float by = bias[col + 1];
            const float r00 = facc[mt][nt][0] + cx01.x + bx;
            const float r01 = facc[mt][nt][1] + cx01.y + by;
            const float r10 = facc[mt][nt][2] + cx23.x + bx;
            const float r11 = facc[mt][nt][3] + cx23.y + by;
            if (mode == 0) {
                const int r0 = rbase + mt * 16;
                float2 o0 = { r00, r01 };
                float2 o1 = { r10, r11 };
                *(float2*)(C + (size_t)r0 * N + col)       = o0;
                *(float2*)(C + (size_t)(r0 + 8) * N + col) = o1;
            } else {
                const int part = col >> 10;          // CTA-uniform (BN=64, head-aligned)
                const int hh   = (col >> 6) & 15;
                const int dd   = col & 63;
#pragma unroll
                for (int rr = 0; rr < 2; rr++) {
                    const int r = rbase + mt * 16 + rr * 8;
                    float v0 = rr ? r10 : r00;
                    float v1 = rr ? r11 : r01;
                    const size_t off =
                        (((size_t)((r >> 11) * 16 + hh)) * SEQ + (r & 2047)) * 64 + dd;
                    if (part == 0) {
                        v0 *= QSCALE; v1 *= QSCALE;
                        *(uint32_t*)(qh + off) = pack2h(__float2half(v0), __float2half(v1));
                    } else {
                        __half* dh = part == 1 ? kh : vh;
                        __half* dl = part == 1 ? kl : vl;
                        const __half h0 = __float2half(v0);
                        const __half h1 = __float2half(v1);
                        *(uint32_t*)(dh + off) = pack2h(h0, h1);
                        *(uint32_t*)(dl + off) =
                            pack2h(__float2half(v0 - __half2float(h0)),
                                   __float2half(v1 - __half2float(h1)));
                    }
                }
            }
        }
    }
}

// ---------------------------------------------------------------------------
// HMMA causal flash attention, fp16-fed, 3-stage cp.async pipeline.
// One CTA = 128 queries of one (b,h); 8 warps x 16 rows; 64-key tiles.
// 2-pass: Q and P single fp16 limb; K and V split hi/lo.
// Main terms f32-acc; cross terms (qh*kl, ph*vl) f16-acc per tile, folded.
// Output written as stacked fp16 [a|a] rows of g_as.
// smem: QH 16K | 3 stages x {KH,KL,VH,VL 8K each} = 112KB
// ---------------------------------------------------------------------------
#define KV_STAGE_BYTES 32768
#define ATTN_SMEM (16384 + 3 * KV_STAGE_BYTES + 128)

__global__ __launch_bounds__(256) void attn_mma_kernel(
    const __half* __restrict__ qh_g,
    const __half* __restrict__ kh_g, const __half* __restrict__ kl_g,
    const __half* __restrict__ vh_g, const __half* __restrict__ vl_g,
    __half* __restrict__ outs)
{
    extern __shared__ char sm[];
    const uint32_t base = (smem_u32(sm) + 127u) & ~127u;
    const uint32_t sQH = base;
    const uint32_t kvbase = base + 16384;

    const int tid  = threadIdx.x;
    const int lane = tid & 31;
    const int wid  = tid >> 5;
    const int qb   = 15 - (int)blockIdx.x;     // heavy blocks first
    const int bh   = blockIdx.y;
    const int b    = bh >> 4;
    const int h    = bh & 15;
    const size_t hrow = (size_t)bh * SEQ;

    // ---- Q tile cp.async (part of group 0): 1024 16B segs ----
#pragma unroll
    for (int i = 0; i < 4; i++) {
        const int s   = i * 256 + tid;
        const int row = s >> 3;
        const int ch  = s & 7;
        const uint32_t sw = (uint32_t)(ch * 16) ^ (uint32_t)((row & 7) << 4);
        const size_t gofs = (hrow + qb * 128 + row) * 64 + ch * 8;
        cp_async16(sQH + row * 128 + sw, qh_g + gofs);
    }

    auto load_kv = [&](int stage, int k0) {
        const uint32_t sb = kvbase + stage * KV_STAGE_BYTES;
#pragma unroll
        for (int i = 0; i < 2; i++) {
            const int s   = i * 256 + tid;
            const int row = s >> 3;
            const int ch  = s & 7;
            const uint32_t sw = (uint32_t)(ch * 16) ^ (uint32_t)((row & 7) << 4);
            const uint32_t so = row * 128 + sw;
            const size_t gofs = (hrow + k0 + row) * 64 + ch * 8;
            cp_async16(sb + so,         kh_g + gofs);
            cp_async16(sb + 8192 + so,  kl_g + gofs);
            cp_async16(sb + 16384 + so, vh_g + gofs);
            cp_async16(sb + 24576 + so, vl_g + gofs);
        }
        CP_COMMIT();
    };

    const int nk = (qb + 1) * 2;
    load_kv(0, 0);
    load_kv(1, 64);

    float acc_o[8][4];
#pragma unroll
    for (int nt = 0; nt < 8; nt++)
#pragma unroll
        for (int r = 0; r < 4; r++) acc_o[nt][r] = 0.0f;
    float m0 = -1e30f, m1 = -1e30f, l0 = 0.0f, l1 = 0.0f;

    const int r0      = lane >> 2;
    const int qrow_w  = qb * 128 + wid * 16;
    const int qg0     = qrow_w + r0;

    const int a_r = wid * 16 + (lane & 15);
    const int a_c = (lane >> 4) * 16;
    const uint32_t a_row_off = (uint32_t)(a_r * 128);
    const uint32_t a_sw = (uint32_t)((a_r & 7) << 4);
    const int g      = lane >> 3;
    const int br_off = lane & 7;

    for (int t = 0; t < nk; t++) {
        const int k0 = t * 64;
        CP_WAIT1();
        __syncthreads();
        if (t + 2 < nk) load_kv((t + 2) % 3, (t + 2) * 64);
        else            CP_COMMIT();

        const uint32_t st  = kvbase + (t % 3) * KV_STAGE_BYTES;
        const uint32_t sKH = st;
        const uint32_t sKL = st + 8192;
        const uint32_t sVH = st + 16384;
        const uint32_t sVL = st + 24576;

        // ---- S = Q K^T: main (qh*kh) f32, cross (qh*kl) f16 ----
        float s[8][4];
        uint32_t scx[8][2];
#pragma unroll
        for (int nt = 0; nt < 8; nt++) {
#pragma unroll
            for (int r = 0; r < 4; r++) s[nt][r] = 0.0f;
            scx[nt][0] = 0u; scx[nt][1] = 0u;
        }

#pragma unroll
        for (int kc = 0; kc < 4; kc++) {
            uint32_t qhf[4];
            const uint32_t qoff = ((uint32_t)(kc * 32 + a_c)) ^ a_sw;
            LDSM_X4(qhf[0], qhf[1], qhf[2], qhf[3], sQH + a_row_off + qoff);
#pragma unroll
            for (int np = 0; np < 4; np++) {
                const int brow = np * 16 + ((g & 2) << 2) + br_off;
                const uint32_t boff = ((uint32_t)(kc * 32 + ((g & 1) << 4)))
                                    ^ (uint32_t)((brow & 7) << 4);
                const uint32_t rb = (uint32_t)(brow * 128) + boff;
                uint32_t kh0, kh1, kh2, kh3, kl0, kl1, kl2, kl3;
                LDSM_X4(kh0, kh1, kh2, kh3, sKH + rb);
                LDSM_X4(kl0, kl1, kl2, kl3, sKL + rb);
                MMAF32(s[2 * np],     qhf, kh0, kh1);
                MMAF32(s[2 * np + 1], qhf, kh2, kh3);
                MMAF16(scx[2 * np],     qhf, kl0, kl1);
                MMAF16(scx[2 * np + 1], qhf, kl2, kl3);
            }
        }
        // fold cross terms
#pragma unroll
        for (int nt = 0; nt < 8; nt++) {
            const float2 cA = __half22float2(*reinterpret_cast<__half2*>(&scx[nt][0]));
            const float2 cB = __half22float2(*reinterpret_cast<__half2*>(&scx[nt][1]));
            s[nt][0] += cA.x; s[nt][1] += cA.y;
            s[nt][2] += cB.x; s[nt][3] += cB.y;
        }

        // ---- causal mask ----
        if (k0 + 63 > qrow_w) {
#pragma unroll
            for (int nt = 0; nt < 8; nt++) {
                const int kg0 = k0 + nt * 8 + 2 * (lane & 3);
                if (kg0     > qg0)     s[nt][0] = -1e30f;
                if (kg0 + 1 > qg0)     s[nt][1] = -1e30f;
                if (kg0     > qg0 + 8) s[nt][2] = -1e30f;
                if (kg0 + 1 > qg0 + 8) s[nt][3] = -1e30f;
            }
        }

        // ---- online softmax (base-2) ----
        float rx0 = -1e30f, rx1 = -1e30f;
#pragma unroll
        for (int nt = 0; nt < 8; nt++) {
            rx0 = fmaxf(rx0, fmaxf(s[nt][0], s[nt][1]));
            rx1 = fmaxf(rx1, fmaxf(s[nt][2], s[nt][3]));
        }
        rx0 = fmaxf(rx0, __shfl_xor_sync(0xffffffffu, rx0, 1));
        rx0 = fmaxf(rx0, __shfl_xor_sync(0xffffffffu, rx0, 2));
        rx1 = fmaxf(rx1, __shfl_xor_sync(0xffffffffu, rx1, 1));
        rx1 = fmaxf(rx1, __shfl_xor_sync(0xffffffffu, rx1, 2));
        const float mn0 = fmaxf(m0, rx0);
        const float mn1 = fmaxf(m1, rx1);
        const float sc0 = fexp2(m0 - mn0);
        const float sc1 = fexp2(m1 - mn1);
        m0 = mn0; m1 = mn1;
        l0 *= sc0; l1 *= sc1;
#pragma unroll
        for (int nt = 0; nt < 8; nt++) {
            acc_o[nt][0] *= sc0; acc_o[nt][1] *= sc0;
            acc_o[nt][2] *= sc1; acc_o[nt][3] *= sc1;
        }

        uint32_t ph[4][4];
#pragma unroll
        for (int nt = 0; nt < 8; nt++) {
            const float p0 = fexp2(s[nt][0] - m0);
            const float p1 = fexp2(s[nt][1] - m0);
            const float p2 = fexp2(s[nt][2] - m1);
            const float p3 = fexp2(s[nt][3] - m1);
            l0 += p0 + p1;
            l1 += p2 + p3;
            const int kc = nt >> 1;
            const int rr = (nt & 1) * 2;
            ph[kc][rr]     = pack2h(__float2half(p0), __float2half(p1));
            ph[kc][rr + 1] = pack2h(__float2half(p2), __float2half(p3));
        }

        // ---- O += P V: main (ph*vh) f32, cross (ph*vl) f16, folded ----
        uint32_t ocx[8][2];
#pragma unroll
        for (int nt = 0; nt < 8; nt++) { ocx[nt][0] = 0u; ocx[nt][1] = 0u; }
#pragma unroll
        for (int kc = 0; kc < 4; kc++) {
#pragma unroll
            for (int np = 0; np < 4; np++) {
                const int vrow = kc * 16 + ((g & 1) << 3) + br_off;
                const uint32_t voff = ((uint32_t)(np * 32 + ((g & 2) << 3)))
                                    ^ (uint32_t)((vrow & 7) << 4);
                const uint32_t rv = (uint32_t)(vrow * 128) + voff;
                uint32_t vh0, vh1, vh2, vh3, vl0, vl1, vl2, vl3;
                LDSM_X4T(vh0, vh1, vh2, vh3, sVH + rv);
                LDSM_X4T(vl0, vl1, vl2, vl3, sVL + rv);
                MMAF32(acc_o[2 * np],     ph[kc], vh0, vh1);
                MMAF32(acc_o[2 * np + 1], ph[kc], vh2, vh3);
                MMAF16(ocx[2 * np],     ph[kc], vl0, vl1);
                MMAF16(ocx[2 * np + 1], ph[kc], vl2, vl3);
            }
        }
#pragma unroll
        for (int nt = 0; nt < 8; nt++) {
            const float2 cA = __half22float2(*reinterpret_cast<__half2*>(&ocx[nt][0]));
            const float2 cB = __half22float2(*reinterpret_cast<__half2*>(&ocx[nt][1]));
            acc_o[nt][0] += cA.x; acc_o[nt][1] += cA.y;
            acc_o[nt][2] += cB.x; acc_o[nt][3] += cB.y;
        }
    }

    // ---- epilogue: normalize, write stacked fp16 [a|a] rows of g_as ----
    l0 += __shfl_xor_sync(0xffffffffu, l0, 1);
    l0 += __shfl_xor_sync(0xffffffffu, l0, 2);
    l1 += __shfl_xor_sync(0xffffffffu, l1, 1);
    l1 += __shfl_xor_sync(0xffffffffu, l1, 2);
    const float inv0 = 1.0f / l0;
    const float inv1 = 1.0f / l1;

    const size_t row0 = (size_t)(b * SEQ + qg0) * KS;
    const size_t row1 = row0 + 8 * KS;
    const int colbase = h * HD + 2 * (lane & 3);
#pragma unroll
    for (int nt = 0; nt < 8; nt++) {
        const int col = colbase + nt * 8;
        const uint32_t o01 = pack2h(__float2half(acc_o[nt][0] * inv0),
                                    __float2half(acc_o[nt][1] * inv0));
        const uint32_t o23 = pack2h(__float2half(acc_o[nt][2] * inv1),
                                    __float2half(acc_o[nt][3] * inv1));
        *(uint32_t*)(outs + row0 + col)        = o01;
        *(uint32_t*)(outs + row0 + col + 1024) = o01;
        *(uint32_t*)(outs + row1 + col)        = o23;
        *(uint32_t*)(outs + row1 + col + 1024) = o23;
    }
}

// ---------------------------------------------------------------------------
extern "C" void kernel_launch(void* const* d_in, const int* in_sizes, int n_in,
                              void* d_out, int out_size)
{
    const float* x     = (const float*)d_in[0];
    const float* w_qkv = (const float*)d_in[1];
    const float* b_qkv = (const float*)d_in[2];
    const float* w_out = (const float*)d_in[3];
    const float* b_out = (const float*)d_in[4];
    float* out = (float*)d_out;

    __half *as, *wqkvs, *wouts, *qh, *kh, *kl, *vh, *vl;
    cudaGetSymbolAddress((void**)&as,    g_as);
    cudaGetSymbolAddress((void**)&wqkvs, g_wqkv_s);
    cudaGetSymbolAddress((void**)&wouts, g_wout_s);
    cudaGetSymbolAddress((void**)&qh, g_qh);
    cudaGetSymbolAddress((void**)&kh, g_kh);
    cudaGetSymbolAddress((void**)&kl, g_kl);
    cudaGetSymbolAddress((void**)&vh, g_vh);
    cudaGetSymbolAddress((void**)&vl, g_vl);

    cudaFuncSetAttribute(mma_gemm_kernel,
                         cudaFuncAttributeMaxDynamicSharedMemorySize, GEMM_SMEM);
    cudaFuncSetAttribute(attn_mma_kernel,
                         cudaFuncAttributeMaxDynamicSharedMemorySize, ATTN_SMEM);

    // 1) Convert weights (transpose + fp16 hi/lo split, K=2048 stack)
    {
        dim3 grid(QKV_N / 32, HID / 32);
        convert_w_kernel<<<grid, 1024>>>(w_qkv, wqkvs, QKV_N);
    }
    {
        dim3 grid(HID / 32, HID / 32);
        convert_w_kernel<<<grid, 1024>>>(w_out, wouts, HID);
    }
    // 2) Convert x (single limb, duplicated)
    convert_act_kernel<<<(MROWS * 1024 + 255) / 256, 256>>>(x, as, MROWS);
    // 3) QKV projection -> head-major fp16 Q / hi-lo K,V (mode 1)
    {
        dim3 grid(QKV_N / BN, MROWS / BM);
        mma_gemm_kernel<<<grid, 256, GEMM_SMEM>>>(as, wqkvs, b_qkv, nullptr,
                                                  QKV_N, 1,
                                                  qh, kh, kl, vh, vl);
    }
    // 4) HMMA flash attention (2-pass) -> stacked fp16 g_as
    {
        dim3 grid(16, BATCH * NHEADS);
        attn_mma_kernel<<<grid, 256, ATTN_SMEM>>>(qh, kh, kl, vh, vl, as);
    }
    // 5) Output projection (mode 0)
    {
        dim3 grid(HID / BN, MROWS / BM);
        mma_gemm_kernel<<<grid, 256, GEMM_SMEM>>>(as, wouts, b_out, out,
                                                  HID, 0,
                                                  nullptr, nullptr, nullptr,
                                                  nullptr, nullptr);
    }
}